// round 5
// baseline (speedup 1.0000x reference)
#include <cuda_runtime.h>
#include <cuda_bf16.h>

#define T_DIM 1024
#define B_DIM 64
#define H_DIM 1024
#define NSPLIT 16
#define OCHUNK (H_DIM / NSPLIT)   // 64

// Scratch (allocation-free rule: __device__ globals)
__device__ float g_partial[NSPLIT * B_DIM * H_DIM];  // 4 MB: [s][b][h]
__device__ float g_v[B_DIM * H_DIM];                 // 256 KB
__device__ float g_energies[B_DIM * T_DIM];          // 256 KB: [b][t]

// ---------------------------------------------------------------------------
// k1: partial[s][b][h] = sum_{o in s-range} hid[b][o] * W[o][h]
// grid (H/256 h-tiles, NSPLIT, B/32), 256 threads. W read exactly once.
// ---------------------------------------------------------------------------
__global__ void __launch_bounds__(256) k1_proj_partial(
    const float* __restrict__ hid, const float* __restrict__ W)
{
    const int h  = blockIdx.x * 256 + threadIdx.x;
    const int o0 = blockIdx.y * OCHUNK;
    const int b0 = blockIdx.z * 32;

    __shared__ float sh[32 * OCHUNK];  // 8 KB
    for (int i = threadIdx.x; i < 32 * OCHUNK; i += 256) {
        int bb = i / OCHUNK;
        int oo = i % OCHUNK;
        sh[i] = hid[(b0 + bb) * H_DIM + o0 + oo];
    }
    __syncthreads();

    float w[OCHUNK];
#pragma unroll
    for (int oo = 0; oo < OCHUNK; oo++)
        w[oo] = W[(o0 + oo) * H_DIM + h];

    float* part = g_partial + blockIdx.y * (B_DIM * H_DIM) + h;

#pragma unroll 4
    for (int bb = 0; bb < 32; bb++) {
        const float4* s4 = reinterpret_cast<const float4*>(sh + bb * OCHUNK);
        float acc = 0.f;
#pragma unroll
        for (int q = 0; q < OCHUNK / 4; q++) {
            float4 x = s4[q];
            acc += x.x * w[4 * q + 0] + x.y * w[4 * q + 1]
                 + x.z * w[4 * q + 2] + x.w * w[4 * q + 3];
        }
        part[(b0 + bb) * H_DIM] = acc;
    }
}

// ---------------------------------------------------------------------------
// k1b: v[i] = sum_s partial[s][i]   (deterministic reduction, no atomics)
// ---------------------------------------------------------------------------
__global__ void __launch_bounds__(256) k1b_reduce()
{
    int i = blockIdx.x * 256 + threadIdx.x;  // 65536 total
    float s = 0.f;
#pragma unroll
    for (int p = 0; p < NSPLIT; p++)
        s += g_partial[p * (B_DIM * H_DIM) + i];
    g_v[i] = s;
}

// ---------------------------------------------------------------------------
// k2: energies[b][t] = <enc[t,b,:], v[b,:]>
// REGISTER-resident v (R3 winner), but TPW=4 for wave smoothing:
// grid (64 b, 32 t-chunks) = 2048 CTAs, 8 warps x 4 rows each.
// 2-row unrolled inner loop -> ~16 LDG.128 in flight per warp;
// launch_bounds(256,2) caps regs at 128 -> >=2 CTAs/SM (16 warps).
// ---------------------------------------------------------------------------
__global__ void __launch_bounds__(256, 2) k2_energies(const float* __restrict__ enc)
{
    const int warp = threadIdx.x >> 5;
    const int lane = threadIdx.x & 31;
    const int b    = blockIdx.x;
    const int t0   = blockIdx.y * 32 + warp * 4;

    // v[b] -> 8 float4 regs (L2/L1-hot, amortized over 4 rows)
    const float4* v4 = reinterpret_cast<const float4*>(g_v + b * H_DIM);
    float4 v[8];
#pragma unroll
    for (int k = 0; k < 8; k++)
        v[k] = v4[lane + 32 * k];

    const size_t row_stride4 = (size_t)B_DIM * H_DIM / 4;   // float4 units
    const float4* e4 = reinterpret_cast<const float4*>(
        enc + ((size_t)t0 * B_DIM + b) * H_DIM) + lane;

    float* eout = g_energies + b * T_DIM + t0;

#pragma unroll
    for (int i = 0; i < 4; i += 2) {
        float acc0 = 0.f, acc1 = 0.f;
#pragma unroll
        for (int k = 0; k < 8; k++) {
            float4 x0 = e4[32 * k];
            float4 x1 = e4[row_stride4 + 32 * k];
            acc0 += x0.x * v[k].x + x0.y * v[k].y + x0.z * v[k].z + x0.w * v[k].w;
            acc1 += x1.x * v[k].x + x1.y * v[k].y + x1.z * v[k].z + x1.w * v[k].w;
        }
#pragma unroll
        for (int off = 16; off; off >>= 1) {
            acc0 += __shfl_xor_sync(0xffffffffu, acc0, off);
            acc1 += __shfl_xor_sync(0xffffffffu, acc1, off);
        }
        if (lane == 0) {
            eout[i]     = acc0;
            eout[i + 1] = acc1;
        }
        e4 += 2 * row_stride4;
    }
}

// ---------------------------------------------------------------------------
// k3: softmax over T for row b. 4 warps per row (128 thr) to cut the serial
// chain: 8 exp/lane, warp shfl + tiny smem combine. Bias dropped
// (softmax shift invariance). grid = 64.
// ---------------------------------------------------------------------------
__global__ void __launch_bounds__(128) k3_softmax(float* __restrict__ out)
{
    const int tid  = threadIdx.x;
    const int warp = tid >> 5;
    const int b    = blockIdx.x;
    __shared__ float red[4];

    const float4* e4 = reinterpret_cast<const float4*>(g_energies + b * T_DIM);
    float4 vals[2];
#pragma unroll
    for (int k = 0; k < 2; k++)
        vals[k] = e4[tid + 128 * k];

    float m = fmaxf(fmaxf(vals[0].x, vals[0].y), fmaxf(vals[0].z, vals[0].w));
    m = fmaxf(m, fmaxf(fmaxf(vals[1].x, vals[1].y), fmaxf(vals[1].z, vals[1].w)));
#pragma unroll
    for (int off = 16; off; off >>= 1)
        m = fmaxf(m, __shfl_xor_sync(0xffffffffu, m, off));
    if ((tid & 31) == 0) red[warp] = m;
    __syncthreads();
    m = fmaxf(fmaxf(red[0], red[1]), fmaxf(red[2], red[3]));

    float lsum = 0.f;
#pragma unroll
    for (int k = 0; k < 2; k++) {
        vals[k].x = __expf(vals[k].x - m);
        vals[k].y = __expf(vals[k].y - m);
        vals[k].z = __expf(vals[k].z - m);
        vals[k].w = __expf(vals[k].w - m);
        lsum += vals[k].x + vals[k].y + vals[k].z + vals[k].w;
    }
#pragma unroll
    for (int off = 16; off; off >>= 1)
        lsum += __shfl_xor_sync(0xffffffffu, lsum, off);
    __syncthreads();
    if ((tid & 31) == 0) red[warp] = lsum;
    __syncthreads();
    const float inv = 1.f / (red[0] + red[1] + red[2] + red[3]);

    float4* o4 = reinterpret_cast<float4*>(out + b * T_DIM);
#pragma unroll
    for (int k = 0; k < 2; k++) {
        float4 r = vals[k];
        r.x *= inv; r.y *= inv; r.z *= inv; r.w *= inv;
        o4[tid + 128 * k] = r;
    }
}

// ---------------------------------------------------------------------------
extern "C" void kernel_launch(void* const* d_in, const int* in_sizes, int n_in,
                              void* d_out, int out_size)
{
    const float* hid = (const float*)d_in[0];   // [1, B, H]
    const float* enc = (const float*)d_in[1];   // [T, B, H]
    const float* W   = (const float*)d_in[2];   // [H, H]
    // d_in[3] = bias: dropped — softmax shift-invariance makes it a no-op.
    float* out = (float*)d_out;                 // [B, 1, T]

    k1_proj_partial<<<dim3(H_DIM / 256, NSPLIT, 2), 256>>>(hid, W);
    k1b_reduce<<<(B_DIM * H_DIM) / 256, 256>>>();
    k2_energies<<<dim3(B_DIM, T_DIM / 32), 256>>>(enc);
    k3_softmax<<<B_DIM, 128>>>(out);
}

// round 6
// speedup vs baseline: 1.0184x; 1.0184x over previous
#include <cuda_runtime.h>
#include <cuda_bf16.h>

#define T_DIM 1024
#define B_DIM 64
#define H_DIM 1024
#define OSPLIT 32                 // o-range per k1 block (R3 winner)

// k2 pipeline geometry
#define RPS 8                     // rows per stage (one per warp)
#define STAGES 4                  // ring depth
#define NSTAGE 16                 // stages per CTA -> 128 rows per CTA
#define STAGE_F4 (RPS * H_DIM / 4)        // float4s per stage (2048)
#define K2_SMEM (STAGES * RPS * H_DIM * 4) // 131072 bytes

// Scratch (allocation-free rule: __device__ globals)
__device__ float g_partial[OSPLIT * B_DIM * H_DIM];  // 8 MB: [s][b][h]
__device__ float g_v[B_DIM * H_DIM];                 // 256 KB
__device__ float g_energies[B_DIM * T_DIM];          // 256 KB: [b][t]

// ---------------------------------------------------------------------------
// k1: partial[s][b][h] = sum_{o in s-range} hid[b][o] * W[o][h]
// grid (H/256, 32, 2), 256 threads. W read exactly once. (R3 config)
// ---------------------------------------------------------------------------
__global__ void __launch_bounds__(256) k1_proj_partial(
    const float* __restrict__ hid, const float* __restrict__ W)
{
    const int h  = blockIdx.x * 256 + threadIdx.x;
    const int o0 = blockIdx.y * OSPLIT;
    const int b0 = blockIdx.z * 32;

    __shared__ float sh[32 * OSPLIT];
    for (int i = threadIdx.x; i < 32 * OSPLIT; i += 256) {
        int bb = i >> 5;
        int oo = i & 31;
        sh[i] = hid[(b0 + bb) * H_DIM + o0 + oo];
    }
    __syncthreads();

    float w[OSPLIT];
#pragma unroll
    for (int oo = 0; oo < OSPLIT; oo++)
        w[oo] = W[(o0 + oo) * H_DIM + h];

    float* part = g_partial + blockIdx.y * (B_DIM * H_DIM) + h;

#pragma unroll
    for (int bb = 0; bb < 32; bb++) {
        const float4* s4 = reinterpret_cast<const float4*>(sh + bb * OSPLIT);
        float acc = 0.f;
#pragma unroll
        for (int q = 0; q < OSPLIT / 4; q++) {
            float4 x = s4[q];
            acc += x.x * w[4 * q + 0] + x.y * w[4 * q + 1]
                 + x.z * w[4 * q + 2] + x.w * w[4 * q + 3];
        }
        part[(b0 + bb) * H_DIM] = acc;
    }
}

// ---------------------------------------------------------------------------
// k1b: v[i] = sum_s partial[s][i]
// ---------------------------------------------------------------------------
__global__ void __launch_bounds__(256) k1b_reduce()
{
    int i = blockIdx.x * 256 + threadIdx.x;
    float s = 0.f;
#pragma unroll
    for (int p = 0; p < OSPLIT; p++)
        s += g_partial[p * (B_DIM * H_DIM) + i];
    g_v[i] = s;
}

// ---------------------------------------------------------------------------
// k2: energies[b][t] = <enc[t,b,:], v[b,:]>
// cp.async.cg pipeline: 4-deep ring of 8-row (32 KB) stages in smem.
// MLP no longer bound by the register file: 64-96 KB in flight per SM.
// Block = (b, 128-row chunk); warp w computes row w of each stage from smem,
// v[b] in 32 registers. grid (64, 8) = 512 CTAs, 1 CTA/SM (128 KB smem).
// ---------------------------------------------------------------------------
__global__ void __launch_bounds__(256) k2_energies(const float* __restrict__ enc)
{
    extern __shared__ float4 sbuf[];     // STAGES * STAGE_F4 float4s
    const int tid  = threadIdx.x;
    const int warp = tid >> 5;
    const int lane = tid & 31;
    const int b    = blockIdx.x;
    const int t0   = blockIdx.y * (NSTAGE * RPS);

    // v[b] -> 8 float4 registers (L2-hot, loaded once)
    const float4* v4 = reinterpret_cast<const float4*>(g_v + b * H_DIM);
    float4 v[8];
#pragma unroll
    for (int k = 0; k < 8; k++)
        v[k] = v4[lane + 32 * k];

    const size_t row_stride = (size_t)B_DIM * H_DIM;      // floats between t's
    const float* base = enc + ((size_t)t0 * B_DIM + b) * H_DIM;

    // Stage s: rows t0 + s*RPS + {0..7}; warp w copies row w (lane: 8x16B).
#define ISSUE_STAGE(s)                                                         \
    do {                                                                       \
        const float* _src = base + (size_t)((s) * RPS + warp) * row_stride;    \
        float4* _dst = sbuf + ((s) & (STAGES - 1)) * STAGE_F4                  \
                            + warp * (H_DIM / 4);                              \
        _Pragma("unroll")                                                      \
        for (int j = 0; j < 8; j++) {                                          \
            unsigned _sa = (unsigned)__cvta_generic_to_shared(                 \
                _dst + lane + 32 * j);                                         \
            asm volatile("cp.async.cg.shared.global [%0], [%1], 16;"           \
                         :: "r"(_sa), "l"(_src + (lane + 32 * j) * 4));        \
        }                                                                      \
        asm volatile("cp.async.commit_group;");                                \
    } while (0)

#pragma unroll
    for (int s = 0; s < STAGES; s++)
        ISSUE_STAGE(s);

    float* eout = g_energies + b * T_DIM + t0;

    for (int s = 0; s < NSTAGE; s++) {
        asm volatile("cp.async.wait_group %0;" :: "n"(STAGES - 1));
        __syncthreads();

        const float4* r4 = sbuf + (s & (STAGES - 1)) * STAGE_F4
                                + warp * (H_DIM / 4);
        float acc = 0.f;
#pragma unroll
        for (int k = 0; k < 8; k++) {
            float4 x = r4[lane + 32 * k];
            acc += x.x * v[k].x + x.y * v[k].y + x.z * v[k].z + x.w * v[k].w;
        }
#pragma unroll
        for (int off = 16; off; off >>= 1)
            acc += __shfl_xor_sync(0xffffffffu, acc, off);
        if (lane == 0)
            eout[s * RPS + warp] = acc;

        __syncthreads();           // buffer (s&3) free before refill
        if (s + STAGES < NSTAGE)
            ISSUE_STAGE(s + STAGES);
        else
            asm volatile("cp.async.commit_group;");  // empty group keeps
                                                     // wait_group<3> aligned
    }
#undef ISSUE_STAGE
}

// ---------------------------------------------------------------------------
// k3: softmax over T per row b — warp per row, one block per row (grid 64).
// Bias dropped (softmax shift invariance). (Measured-best shape.)
// ---------------------------------------------------------------------------
__global__ void __launch_bounds__(32) k3_softmax(float* __restrict__ out)
{
    const int lane = threadIdx.x;
    const int b    = blockIdx.x;

    const float4* e4 = reinterpret_cast<const float4*>(g_energies + b * T_DIM);
    float4 vals[8];
#pragma unroll
    for (int k = 0; k < 8; k++)
        vals[k] = e4[lane + 32 * k];

    float m = -1e30f;
#pragma unroll
    for (int k = 0; k < 8; k++)
        m = fmaxf(m, fmaxf(fmaxf(vals[k].x, vals[k].y), fmaxf(vals[k].z, vals[k].w)));
#pragma unroll
    for (int off = 16; off; off >>= 1)
        m = fmaxf(m, __shfl_xor_sync(0xffffffffu, m, off));

    float lsum = 0.f;
#pragma unroll
    for (int k = 0; k < 8; k++) {
        vals[k].x = __expf(vals[k].x - m);
        vals[k].y = __expf(vals[k].y - m);
        vals[k].z = __expf(vals[k].z - m);
        vals[k].w = __expf(vals[k].w - m);
        lsum += vals[k].x + vals[k].y + vals[k].z + vals[k].w;
    }
#pragma unroll
    for (int off = 16; off; off >>= 1)
        lsum += __shfl_xor_sync(0xffffffffu, lsum, off);
    const float inv = 1.f / lsum;

    float4* o4 = reinterpret_cast<float4*>(out + b * T_DIM);
#pragma unroll
    for (int k = 0; k < 8; k++) {
        float4 r = vals[k];
        r.x *= inv; r.y *= inv; r.z *= inv; r.w *= inv;
        o4[lane + 32 * k] = r;
    }
}

// ---------------------------------------------------------------------------
extern "C" void kernel_launch(void* const* d_in, const int* in_sizes, int n_in,
                              void* d_out, int out_size)
{
    const float* hid = (const float*)d_in[0];   // [1, B, H]
    const float* enc = (const float*)d_in[1];   // [T, B, H]
    const float* W   = (const float*)d_in[2];   // [H, H]
    // d_in[3] = bias: dropped — softmax shift-invariance makes it a no-op.
    float* out = (float*)d_out;                 // [B, 1, T]

    static int smem_set = 0;
    if (!smem_set) {
        cudaFuncSetAttribute(k2_energies,
                             cudaFuncAttributeMaxDynamicSharedMemorySize,
                             K2_SMEM);
        smem_set = 1;
    }

    k1_proj_partial<<<dim3(H_DIM / 256, OSPLIT, 2), 256>>>(hid, W);
    k1b_reduce<<<(B_DIM * H_DIM) / 256, 256>>>();
    k2_energies<<<dim3(B_DIM, T_DIM / (NSTAGE * RPS)), 256, K2_SMEM>>>(enc);
    k3_softmax<<<B_DIM, 32>>>(out);
}